// round 1
// baseline (speedup 1.0000x reference)
#include <cuda_runtime.h>
#include <cuda_bf16.h>
#include <math_constants.h>

#define NB 8192
#define HWN 4096   // 64*64
#define THREADS 128

__device__ float g_partial[NB];

__global__ void __launch_bounds__(THREADS, 8)
per_sample_kernel(const float* __restrict__ x) {
    const int b = blockIdx.x;
    const int t = threadIdx.x;
    const float4* __restrict__ xp =
        reinterpret_cast<const float4*>(x + (size_t)b * HWN);

    float s0 = 0.f, sj = 0.f, sk = 0.f, sq = 0.f;
    float bv = -CUDART_INF_F;
    int   bi = HWN;  // sentinel larger than any valid index

    #pragma unroll
    for (int it = 0; it < 8; ++it) {
        const int q = it * THREADS + t;     // float4 index within sample
        const float4 v = xp[q];
        const int l  = q << 2;              // flat element index
        const int j  = l >> 6;
        const int k0 = l & 63;
        const float jf = (float)j;
        const float j2 = jf * jf;

        float vals[4] = {v.x, v.y, v.z, v.w};
        #pragma unroll
        for (int c = 0; c < 4; ++c) {
            const float xv = vals[c];
            const float kf = (float)(k0 + c);
            s0 += xv;
            sj  = fmaf(jf, xv, sj);
            sk  = fmaf(kf, xv, sk);
            sq  = fmaf(j2 + kf * kf, xv, sq);
            const int li = l + c;
            // first-max semantics: strictly greater replaces; on tie keep
            // the smaller flat index
            if (xv > bv || (xv == bv && li < bi)) { bv = xv; bi = li; }
        }
    }

    // ---- warp reduction ----
    #pragma unroll
    for (int off = 16; off > 0; off >>= 1) {
        s0 += __shfl_down_sync(0xffffffffu, s0, off);
        sj += __shfl_down_sync(0xffffffffu, sj, off);
        sk += __shfl_down_sync(0xffffffffu, sk, off);
        sq += __shfl_down_sync(0xffffffffu, sq, off);
        const float ov = __shfl_down_sync(0xffffffffu, bv, off);
        const int   oi = __shfl_down_sync(0xffffffffu, bi, off);
        if (ov > bv || (ov == bv && oi < bi)) { bv = ov; bi = oi; }
    }

    // ---- cross-warp reduction via shared ----
    __shared__ float sh_s0[4], sh_sj[4], sh_sk[4], sh_sq[4], sh_bv[4];
    __shared__ int   sh_bi[4];
    const int wid = t >> 5;
    const int lid = t & 31;
    if (lid == 0) {
        sh_s0[wid] = s0; sh_sj[wid] = sj; sh_sk[wid] = sk; sh_sq[wid] = sq;
        sh_bv[wid] = bv; sh_bi[wid] = bi;
    }
    __syncthreads();

    if (t == 0) {
        float fs0 = sh_s0[0], fsj = sh_sj[0], fsk = sh_sk[0], fsq = sh_sq[0];
        float fbv = sh_bv[0]; int fbi = sh_bi[0];
        #pragma unroll
        for (int w = 1; w < 4; ++w) {
            fs0 += sh_s0[w]; fsj += sh_sj[w]; fsk += sh_sk[w]; fsq += sh_sq[w];
            const float ov = sh_bv[w]; const int oi = sh_bi[w];
            if (ov > fbv || (ov == fbv && oi < fbi)) { fbv = ov; fbi = oi; }
        }
        const float mx = (float)(fbi >> 6);
        const float my = (float)(fbi & 63);
        const float loss = (mx * mx + my * my) * fs0
                         - 2.f * mx * fsj
                         - 2.f * my * fsk
                         + fsq;
        g_partial[b] = loss;
    }
}

__global__ void __launch_bounds__(1024, 1)
final_reduce_kernel(float* __restrict__ out) {
    __shared__ double sh[1024];
    const int t = threadIdx.x;
    double d = 0.0;
    #pragma unroll
    for (int i = t; i < NB; i += 1024) d += (double)g_partial[i];
    sh[t] = d;
    __syncthreads();
    #pragma unroll
    for (int s = 512; s > 0; s >>= 1) {
        if (t < s) sh[t] += sh[t + s];
        __syncthreads();
    }
    if (t == 0) out[0] = (float)sh[0];
}

extern "C" void kernel_launch(void* const* d_in, const int* in_sizes, int n_in,
                              void* d_out, int out_size) {
    const float* x = (const float*)d_in[0];
    float* out = (float*)d_out;
    per_sample_kernel<<<NB, THREADS>>>(x);
    final_reduce_kernel<<<1, 1024>>>(out);
}

// round 2
// speedup vs baseline: 1.4474x; 1.4474x over previous
#include <cuda_runtime.h>
#include <cuda_bf16.h>
#include <math_constants.h>

#define NB 8192
#define THREADS 128
#define FP_SCALE 32768.0f   // 2^15 fixed-point scale (deterministic integer sum)

// Allocation-free scratch: zero-initialized device globals.
// g_acc / g_done are reset by the last CTA each launch -> replay-safe.
__device__ unsigned long long g_acc;
__device__ unsigned int g_done;

__global__ void __launch_bounds__(THREADS)
loss_fused_kernel(const float* __restrict__ x, float* __restrict__ out) {
    const int b = blockIdx.x;
    const int t = threadIdx.x;
    const float4* __restrict__ xp =
        reinterpret_cast<const float4*>(x) + (size_t)b * 1024 + t;

    // Thread-constant geometry: q = it*128 + t
    //   j  = q>>4 = it*8 + (t>>4)    (row)
    //   k0 = (q&15)*4 = (t&15)*4     (constant across iterations!)
    const int   tk = t & 15;
    const int   jb = t >> 4;
    const float k0 = (float)(tk << 2);

    // Front-batch all loads (MLP=8), streaming hint (read-once data)
    float4 v[8];
    #pragma unroll
    for (int it = 0; it < 8; ++it) v[it] = __ldcs(&xp[it * THREADS]);

    float s0 = 0.f, sm1 = 0.f, sm2 = 0.f, sj = 0.f, sjj = 0.f;
    float bv = -CUDART_INF_F;
    int   bi = 0x7fffffff;

    #pragma unroll
    for (int it = 0; it < 8; ++it) {
        const float X = v[it].x, Y = v[it].y, Z = v[it].z, W = v[it].w;
        const int   ji = it * 8 + jb;
        const float jf = (float)ji;

        const float ls = (X + Y) + (Z + W);
        const float m1 = fmaf(3.f, W, fmaf(2.f, Z, Y)); // sum c*x_c
        const float m2 = fmaf(9.f, W, fmaf(4.f, Z, Y)); // sum c^2*x_c

        s0  += ls;
        sm1 += m1;
        sm2 += m2;
        sj   = fmaf(jf, ls, sj);
        sjj  = fmaf(jf * jf, ls, sjj);

        // argmax: cheap quad-max, rare update branch; within-thread indices
        // are monotone increasing so strict '>' keeps the first max.
        const float m = fmaxf(fmaxf(X, Y), fmaxf(Z, W));
        if (m > bv) {
            bv = m;
            const int c = (m == X) ? 0 : ((m == Y) ? 1 : ((m == Z) ? 2 : 3));
            bi = (ji << 6) + (tk << 2) + c;
        }
    }

    // Fold thread-constant k0 terms
    float sk = fmaf(k0, s0, sm1);                                  // sum k*x
    float sq = fmaf(k0 * k0, s0, fmaf(2.f * k0, sm1, sm2)) + sjj;  // sum (j^2+k^2)*x

    // ---- warp reduction ----
    #pragma unroll
    for (int off = 16; off > 0; off >>= 1) {
        s0 += __shfl_down_sync(0xffffffffu, s0, off);
        sj += __shfl_down_sync(0xffffffffu, sj, off);
        sk += __shfl_down_sync(0xffffffffu, sk, off);
        sq += __shfl_down_sync(0xffffffffu, sq, off);
        const float ov = __shfl_down_sync(0xffffffffu, bv, off);
        const int   oi = __shfl_down_sync(0xffffffffu, bi, off);
        if (ov > bv || (ov == bv && oi < bi)) { bv = ov; bi = oi; }
    }

    // ---- cross-warp reduction ----
    __shared__ float sh_s0[4], sh_sj[4], sh_sk[4], sh_sq[4], sh_bv[4];
    __shared__ int   sh_bi[4];
    const int wid = t >> 5;
    if ((t & 31) == 0) {
        sh_s0[wid] = s0; sh_sj[wid] = sj; sh_sk[wid] = sk; sh_sq[wid] = sq;
        sh_bv[wid] = bv; sh_bi[wid] = bi;
    }
    __syncthreads();

    if (t == 0) {
        float fs0 = sh_s0[0], fsj = sh_sj[0], fsk = sh_sk[0], fsq = sh_sq[0];
        float fbv = sh_bv[0]; int fbi = sh_bi[0];
        #pragma unroll
        for (int w = 1; w < 4; ++w) {
            fs0 += sh_s0[w]; fsj += sh_sj[w]; fsk += sh_sk[w]; fsq += sh_sq[w];
            const float ov = sh_bv[w]; const int oi = sh_bi[w];
            if (ov > fbv || (ov == fbv && oi < fbi)) { fbv = ov; fbi = oi; }
        }
        const float mx = (float)(fbi >> 6);
        const float my = (float)(fbi & 63);
        const float loss = (mx * mx + my * my) * fs0
                         - 2.f * mx * fsj
                         - 2.f * my * fsk
                         + fsq;

        // Deterministic fixed-point accumulation (integer add is associative)
        const long long q = llrintf(loss * FP_SCALE);
        atomicAdd(&g_acc, (unsigned long long)q);
        __threadfence();
        const unsigned int n = atomicAdd(&g_done, 1u);
        if (n == NB - 1u) {
            // last CTA: all adds are L2-visible (fence-before-counter ordering)
            const long long tot = (long long)atomicExch(&g_acc, 0ULL);
            g_done = 0;
            out[0] = (float)((double)tot / (double)FP_SCALE);
        }
    }
}

extern "C" void kernel_launch(void* const* d_in, const int* in_sizes, int n_in,
                              void* d_out, int out_size) {
    const float* x = (const float*)d_in[0];
    float* out = (float*)d_out;
    loss_fused_kernel<<<NB, THREADS>>>(x, out);
}